// round 11
// baseline (speedup 1.0000x reference)
#include <cuda_runtime.h>
#include <cuda_fp16.h>
#include <cstdint>

#define DI __device__ __forceinline__

namespace {

constexpr int kT = 28;
constexpr int kI = 28;
constexpr int kH = 128;
constexpr int kC = 10;
constexpr int WARPS = 4;
constexpr int THREADS = WARPS * 32;                 // 128
constexpr int TILES = 32768 / 16;                   // 2048 warp-tiles (m16)
constexpr int GRID = TILES / WARPS;                 // 512
constexpr int XROW = kT * kI;                       // 784

// SMEM: paired-B fragment tables. One uint4 per lane per (kt, nt-pair)
// = B fragments for two consecutive n-tiles -> one LDS.128 feeds two MMAs.
constexpr unsigned OFF_W = 0;                   // [8kt][8ntp][32 lane][16B] = 32768
constexpr unsigned OFF_U = 32768;               // [2kt][8ntp][32][16B]     = 8192
constexpr unsigned OFF_V = 32768 + 8192;        // [8kt][1ntp][32][16B]     = 4096
constexpr unsigned SMEM_TOTAL = OFF_V + 4096;   // 45056 -> 4 CTAs/SM (176 KB)

// pack two fp32 -> fp16x2 (lo = a, hi = b)
DI unsigned packh(float a, float b) {
  unsigned d;
  asm("cvt.rn.f16x2.f32 %0, %1, %2;" : "=r"(d) : "f"(b), "f"(a));
  return d;
}
DI unsigned packh2(float2 v) { return packh(v.x, v.y); }

DI unsigned th2(unsigned h2) {  // tanh on fp16x2, one MUFU per 2 elems
  unsigned r;
  asm("tanh.approx.f16x2 %0, %1;" : "=r"(r) : "r"(h2));
  return r;
}

// f16-accumulator MMA: D(f16x2 x2) += A(m16k16 f16) * B(k16n8 f16)
DI void mmah(unsigned* d, const unsigned* a, unsigned bx, unsigned by) {
  asm("mma.sync.aligned.m16n8k16.row.col.f16.f16.f16.f16 "
      "{%0,%1},{%2,%3,%4,%5},{%6,%7},{%0,%1};"
      : "+r"(d[0]), "+r"(d[1])
      : "r"(a[0]), "r"(a[1]), "r"(a[2]), "r"(a[3]), "r"(bx), "r"(by));
}
DI void mmahz(unsigned* d, const unsigned* a, unsigned bx, unsigned by) {
  asm("mma.sync.aligned.m16n8k16.row.col.f16.f16.f16.f16 "
      "{%0,%1},{%2,%3,%4,%5},{%6,%7},{%8,%8};"
      : "=r"(d[0]), "=r"(d[1])
      : "r"(a[0]), "r"(a[1]), "r"(a[2]), "r"(a[3]), "r"(bx), "r"(by),
        "r"(0u));
}
// f32-accumulator MMA (output projection only, outside the hot loop)
DI void mma16(float* c, const unsigned* a, unsigned bx, unsigned by) {
  asm("mma.sync.aligned.m16n8k16.row.col.f32.f16.f16.f32 "
      "{%0,%1,%2,%3},{%4,%5,%6,%7},{%8,%9},{%0,%1,%2,%3};"
      : "+f"(c[0]), "+f"(c[1]), "+f"(c[2]), "+f"(c[3])
      : "r"(a[0]), "r"(a[1]), "r"(a[2]), "r"(a[3]), "r"(bx), "r"(by));
}
DI void mma16z(float* c, const unsigned* a, unsigned bx, unsigned by) {
  asm("mma.sync.aligned.m16n8k16.row.col.f32.f16.f16.f32 "
      "{%0,%1,%2,%3},{%4,%5,%6,%7},{%8,%9},{%10,%10,%10,%10};"
      : "=f"(c[0]), "=f"(c[1]), "=f"(c[2]), "=f"(c[3])
      : "r"(a[0]), "r"(a[1]), "r"(a[2]), "r"(a[3]), "r"(bx), "r"(by),
        "f"(0.0f));
}

// B element (n,k) -> byte offset inside a paired table with `ntpn` nt-pairs
// (kt stride = ntpn * 32 uint4). W: ntpn=8, U: ntpn=8, V: ntpn=1.
DI unsigned bpos(int n, int k, int ntpn) {
  int kt = k >> 4, kk = k & 15, nt = n >> 3, rr = n & 7;
  int ntp = nt >> 1, sel = nt & 1;
  int ln = rr * 4 + ((kk >> 1) & 3);
  return (unsigned)((((kt * ntpn + ntp) * 32 + ln) << 4) + sel * 8 +
                    ((kk >> 3) & 1) * 4 + (kk & 1) * 2);
}

__global__ void __launch_bounds__(THREADS, 4) rnn_kernel(
    const float* __restrict__ x, const float* __restrict__ Uw,
    const float* __restrict__ Ub, const float* __restrict__ Ww,
    const float* __restrict__ Wb, const float* __restrict__ Vw,
    const float* __restrict__ Vb, float* __restrict__ out) {
  extern __shared__ __align__(16) char sm[];
  const int tid = threadIdx.x;
  const int w = tid >> 5, lane = tid & 31;
  const int r = lane >> 2, q = lane & 3;

  // ---- build fp16 paired-B fragment tables, biases folded into U col 28 ----
  for (int idx = tid; idx < kH * kH; idx += THREADS) {  // W^T[k][n] = Ww[n*128+k]
    int n = idx >> 7, k = idx & 127;
    *(__half*)(sm + OFF_W + bpos(n, k, 8)) = __float2half_rn(Ww[idx]);
  }
  for (int idx = tid; idx < kH * 32; idx += THREADS) {  // U^T padded K=32
    int n = idx >> 5, k = idx & 31;
    float v = (k < kI) ? Uw[n * kI + k] : ((k == kI) ? (Ub[n] + Wb[n]) : 0.0f);
    *(__half*)(sm + OFF_U + bpos(n, k, 8)) = __float2half_rn(v);
  }
  for (int idx = tid; idx < 16 * kH; idx += THREADS) {  // V^T padded N=16
    int n = idx >> 7, k = idx & 127;
    float v = (n < kC) ? Vw[n * kH + k] : 0.0f;
    *(__half*)(sm + OFF_V + bpos(n, k, 1)) = __float2half_rn(v);
  }
  __syncthreads();

  const int g = blockIdx.x * WARPS + w;  // global warp-tile (16 batch rows)

  // lane's A-fragment rows: g*16 + r and g*16 + r + 8
  const float* xbase = x + (long)(g * 16 + r) * XROW;
  const uint4* Utab = (const uint4*)(sm + OFF_U) + lane;
  const uint4* Wtab = (const uint4*)(sm + OFF_W) + lane;

  // A-fragments of [x_t | 1 | 0pad]; converted at load, no raw staging regs
  unsigned xf[2][4];
  {
    const unsigned cpad = (q == 2) ? 0x00003C00u : 0u;  // cols 28..31 = 1,0,0,0
    if (q >= 2) { xf[1][2] = cpad; xf[1][3] = cpad; }
  }
  auto ldxf = [&](int t) {
    const float* p0 = xbase + t * kI + 2 * q;
    const float* p1 = p0 + 8 * XROW;
    xf[0][0] = packh2(*(const float2*)(p0));
    xf[0][1] = packh2(*(const float2*)(p1));
    xf[0][2] = packh2(*(const float2*)(p0 + 8));
    xf[0][3] = packh2(*(const float2*)(p1 + 8));
    xf[1][0] = packh2(*(const float2*)(p0 + 16));
    xf[1][1] = packh2(*(const float2*)(p1 + 16));
    if (q < 2) {  // q>=2 would read past row end on the last row
      xf[1][2] = packh2(*(const float2*)(p0 + 24));
      xf[1][3] = packh2(*(const float2*)(p1 + 24));
    }
  };
  ldxf(0);

  // State / accumulator ping-pong. H[nt][j]: f16x2 C-tile regs.
  // Key identity: A-fragment for k-tile kt of S == {H[2kt][0],H[2kt][1],
  // H[2kt+1][0],H[2kt+1][1]} == &H[2*kt][0] (contiguous). No transpose needed.
  unsigned H0[16][2], H1[16][2];

  // One step: reads Hin as S_{t-1} fragments, writes tanh(z_t) into Hout.
  auto step = [&](unsigned(&Hin)[16][2], unsigned(&Hout)[16][2], int t) {
    // U part: Hout = x_t @ U^T (+ biases); kt=0 initializes
#pragma unroll
    for (int i = 0; i < 8; i++) {
      uint4 bb = Utab[i * 32];
      mmahz(Hout[2 * i], xf[0], bb.x, bb.y);
      mmahz(Hout[2 * i + 1], xf[0], bb.z, bb.w);
    }
#pragma unroll
    for (int i = 0; i < 8; i++) {
      uint4 bb = Utab[256 + i * 32];
      mmah(Hout[2 * i], xf[1], bb.x, bb.y);
      mmah(Hout[2 * i + 1], xf[1], bb.z, bb.w);
    }
    // prefetch + convert x_{t+1} NOW (xf dead after U part): the 128 W-MMAs
    // below (~900 cyc) cover the DRAM latency of these LDGs.
    if (t + 1 < kT) ldxf(t + 1);
    // W part: Hout += S_{t-1} @ W^T (one LDS.128 feeds two MMAs)
    if (t > 0) {
#pragma unroll
      for (int kt = 0; kt < 8; kt++) {
        const unsigned* a = &Hin[2 * kt][0];  // A-fragment alias
#pragma unroll
        for (int i = 0; i < 8; i++) {
          uint4 b = Wtab[(kt * 8 + i) * 32];
          mmah(Hout[2 * i], a, b.x, b.y);
          mmah(Hout[2 * i + 1], a, b.z, b.w);
        }
      }
    }
    // transform: S_t = tanh(z_t), in place, 1 MUFU per 2 elements
#pragma unroll
    for (int i = 0; i < 16; i++) {
      Hout[i][0] = th2(Hout[i][0]);
      Hout[i][1] = th2(Hout[i][1]);
    }
  };

#pragma unroll 1
  for (int t = 0; t < kT; t += 2) {
    step(H0, H1, t);      // S_t     -> H1
    step(H1, H0, t + 1);  // S_{t+1} -> H0
  }
  // final state fragments in H0

  // output: out = S @ V^T + V_b (fp32 accum; N padded to 16, kt stride 32)
  float o0[4], o1[4];
  {
    const uint4* bb = (const uint4*)(sm + OFF_V) + lane;
    uint4 b = bb[0];
    mma16z(o0, &H0[0][0], b.x, b.y);
    mma16z(o1, &H0[0][0], b.z, b.w);
#pragma unroll
    for (int kt = 1; kt < 8; kt++) {
      b = bb[kt * 32];
      mma16(o0, &H0[2 * kt][0], b.x, b.y);
      mma16(o1, &H0[2 * kt][0], b.z, b.w);
    }
  }
  const float vb0 = __ldg(Vb + 2 * q), vb1 = __ldg(Vb + 2 * q + 1);
  const int row0 = g * 16 + r;
  *(float2*)(out + row0 * kC + 2 * q) = make_float2(o0[0] + vb0, o0[1] + vb1);
  *(float2*)(out + (row0 + 8) * kC + 2 * q) =
      make_float2(o0[2] + vb0, o0[3] + vb1);
  if (q == 0) {
    const float vb8 = __ldg(Vb + 8), vb9 = __ldg(Vb + 9);
    *(float2*)(out + row0 * kC + 8) = make_float2(o1[0] + vb8, o1[1] + vb9);
    *(float2*)(out + (row0 + 8) * kC + 8) =
        make_float2(o1[2] + vb8, o1[3] + vb9);
  }
}

}  // namespace

extern "C" void kernel_launch(void* const* d_in, const int* in_sizes, int n_in,
                              void* d_out, int out_size) {
  (void)in_sizes; (void)n_in; (void)out_size;
  cudaFuncSetAttribute(rnn_kernel, cudaFuncAttributeMaxDynamicSharedMemorySize,
                       SMEM_TOTAL);
  rnn_kernel<<<GRID, THREADS, SMEM_TOTAL>>>(
      (const float*)d_in[0], (const float*)d_in[1], (const float*)d_in[2],
      (const float*)d_in[3], (const float*)d_in[4], (const float*)d_in[5],
      (const float*)d_in[6], (float*)d_out);
}

// round 12
// speedup vs baseline: 2.2065x; 2.2065x over previous
#include <cuda_runtime.h>
#include <cuda_fp16.h>
#include <cstdint>

#define DI __device__ __forceinline__

namespace {

constexpr int kT = 28;
constexpr int kI = 28;
constexpr int kH = 128;
constexpr int kC = 10;
constexpr int WARPS = 4;
constexpr int THREADS = WARPS * 32;                 // 128
constexpr int TILES = 32768 / 16;                   // 2048 warp-tiles (m16)
constexpr int GRID = TILES / WARPS;                 // 512
constexpr int XROW = kT * kI;                       // 784

// SMEM: paired-B fragment tables. One uint4 per lane per (kt, nt-pair)
// = B fragments for two consecutive n-tiles -> one LDS.128 feeds two MMAs.
constexpr unsigned OFF_W = 0;                   // [8kt][8ntp][32 lane][16B] = 32768
constexpr unsigned OFF_U = 32768;               // [2kt][8ntp][32][16B]     = 8192
constexpr unsigned OFF_V = 32768 + 8192;        // [8kt][1ntp][32][16B]     = 4096
constexpr unsigned SMEM_TOTAL = OFF_V + 4096;   // 45056 -> 4 CTAs/SM (176 KB)

// pack two fp32 -> fp16x2 (lo = a, hi = b)
DI unsigned packh(float a, float b) {
  unsigned d;
  asm("cvt.rn.f16x2.f32 %0, %1, %2;" : "=r"(d) : "f"(b), "f"(a));
  return d;
}
DI unsigned packh2(float2 v) { return packh(v.x, v.y); }

DI unsigned th2(unsigned h2) {  // tanh on fp16x2, one MUFU per 2 elems
  unsigned r;
  asm("tanh.approx.f16x2 %0, %1;" : "=r"(r) : "r"(h2));
  return r;
}

// f16-accumulator MMA: D(f16x2 x2) += A(m16k16 f16) * B(k16n8 f16)
DI void mmah(unsigned* d, const unsigned* a, unsigned bx, unsigned by) {
  asm("mma.sync.aligned.m16n8k16.row.col.f16.f16.f16.f16 "
      "{%0,%1},{%2,%3,%4,%5},{%6,%7},{%0,%1};"
      : "+r"(d[0]), "+r"(d[1])
      : "r"(a[0]), "r"(a[1]), "r"(a[2]), "r"(a[3]), "r"(bx), "r"(by));
}
DI void mmahz(unsigned* d, const unsigned* a, unsigned bx, unsigned by) {
  asm("mma.sync.aligned.m16n8k16.row.col.f16.f16.f16.f16 "
      "{%0,%1},{%2,%3,%4,%5},{%6,%7},{%8,%8};"
      : "=r"(d[0]), "=r"(d[1])
      : "r"(a[0]), "r"(a[1]), "r"(a[2]), "r"(a[3]), "r"(bx), "r"(by),
        "r"(0u));
}
// f32-accumulator MMA (output projection only, outside the hot loop)
DI void mma16(float* c, const unsigned* a, unsigned bx, unsigned by) {
  asm("mma.sync.aligned.m16n8k16.row.col.f32.f16.f16.f32 "
      "{%0,%1,%2,%3},{%4,%5,%6,%7},{%8,%9},{%0,%1,%2,%3};"
      : "+f"(c[0]), "+f"(c[1]), "+f"(c[2]), "+f"(c[3])
      : "r"(a[0]), "r"(a[1]), "r"(a[2]), "r"(a[3]), "r"(bx), "r"(by));
}
DI void mma16z(float* c, const unsigned* a, unsigned bx, unsigned by) {
  asm("mma.sync.aligned.m16n8k16.row.col.f32.f16.f16.f32 "
      "{%0,%1,%2,%3},{%4,%5,%6,%7},{%8,%9},{%10,%10,%10,%10};"
      : "=f"(c[0]), "=f"(c[1]), "=f"(c[2]), "=f"(c[3])
      : "r"(a[0]), "r"(a[1]), "r"(a[2]), "r"(a[3]), "r"(bx), "r"(by),
        "f"(0.0f));
}

// B element (n,k) -> byte offset inside a paired table with `ntpn` nt-pairs
// (kt stride = ntpn * 32 uint4). W: ntpn=8, U: ntpn=8, V: ntpn=1.
DI unsigned bpos(int n, int k, int ntpn) {
  int kt = k >> 4, kk = k & 15, nt = n >> 3, rr = n & 7;
  int ntp = nt >> 1, sel = nt & 1;
  int ln = rr * 4 + ((kk >> 1) & 3);
  return (unsigned)((((kt * ntpn + ntp) * 32 + ln) << 4) + sel * 8 +
                    ((kk >> 3) & 1) * 4 + (kk & 1) * 2);
}

__global__ void __launch_bounds__(THREADS, 4) rnn_kernel(
    const float* __restrict__ x, const float* __restrict__ Uw,
    const float* __restrict__ Ub, const float* __restrict__ Ww,
    const float* __restrict__ Wb, const float* __restrict__ Vw,
    const float* __restrict__ Vb, float* __restrict__ out) {
  extern __shared__ __align__(16) char sm[];
  const int tid = threadIdx.x;
  const int w = tid >> 5, lane = tid & 31;
  const int r = lane >> 2, q = lane & 3;

  // ---- build fp16 paired-B fragment tables, biases folded into U col 28 ----
  for (int idx = tid; idx < kH * kH; idx += THREADS) {  // W^T[k][n] = Ww[n*128+k]
    int n = idx >> 7, k = idx & 127;
    *(__half*)(sm + OFF_W + bpos(n, k, 8)) = __float2half_rn(Ww[idx]);
  }
  for (int idx = tid; idx < kH * 32; idx += THREADS) {  // U^T padded K=32
    int n = idx >> 5, k = idx & 31;
    float v = (k < kI) ? Uw[n * kI + k] : ((k == kI) ? (Ub[n] + Wb[n]) : 0.0f);
    *(__half*)(sm + OFF_U + bpos(n, k, 8)) = __float2half_rn(v);
  }
  for (int idx = tid; idx < 16 * kH; idx += THREADS) {  // V^T padded N=16
    int n = idx >> 7, k = idx & 127;
    float v = (n < kC) ? Vw[n * kH + k] : 0.0f;
    *(__half*)(sm + OFF_V + bpos(n, k, 1)) = __float2half_rn(v);
  }
  __syncthreads();

  const int g = blockIdx.x * WARPS + w;  // global warp-tile (16 batch rows)

  // lane's A-fragment rows: g*16 + r and g*16 + r + 8
  const float* xbase = x + (long)(g * 16 + r) * XROW;
  const uint4* Utab = (const uint4*)(sm + OFF_U) + lane;
  const uint4* Wtab = (const uint4*)(sm + OFF_W) + lane;

  // A-fragments of [x_t | 1 | 0pad]; converted at load, no raw staging regs
  unsigned xf[2][4];
  {
    const unsigned cpad = (q == 2) ? 0x00003C00u : 0u;  // cols 28..31 = 1,0,0,0
    if (q >= 2) { xf[1][2] = cpad; xf[1][3] = cpad; }
  }
  auto ldxf = [&](int t) {
    const float* p0 = xbase + t * kI + 2 * q;
    const float* p1 = p0 + 8 * XROW;
    xf[0][0] = packh2(*(const float2*)(p0));
    xf[0][1] = packh2(*(const float2*)(p1));
    xf[0][2] = packh2(*(const float2*)(p0 + 8));
    xf[0][3] = packh2(*(const float2*)(p1 + 8));
    xf[1][0] = packh2(*(const float2*)(p0 + 16));
    xf[1][1] = packh2(*(const float2*)(p1 + 16));
    if (q < 2) {  // q>=2 would read past row end on the last row
      xf[1][2] = packh2(*(const float2*)(p0 + 24));
      xf[1][3] = packh2(*(const float2*)(p1 + 24));
    }
  };
  ldxf(0);

  // Persistent state: S_{t-1} A-fragments (fp16x2). Single array, no ping-pong.
  unsigned A[8][4];

#pragma unroll 1
  for (int t = 0; t < kT; t++) {
    // Fresh f16x2 accumulators each iteration (the tanh transform below moves
    // them into A, so no double-buffering of register arrays is ever needed).
    unsigned C[16][2];
    // U part: C = x_t @ U^T (+ biases); kt=0 initializes
#pragma unroll
    for (int i = 0; i < 8; i++) {
      uint4 bb = Utab[i * 32];
      mmahz(C[2 * i], xf[0], bb.x, bb.y);
      mmahz(C[2 * i + 1], xf[0], bb.z, bb.w);
    }
#pragma unroll
    for (int i = 0; i < 8; i++) {
      uint4 bb = Utab[256 + i * 32];
      mmah(C[2 * i], xf[1], bb.x, bb.y);
      mmah(C[2 * i + 1], xf[1], bb.z, bb.w);
    }
    // prefetch + convert x_{t+1} now (xf dead after U part): the 128 W-MMAs
    // below cover the DRAM latency of these LDGs.
    if (t + 1 < kT) ldxf(t + 1);
    // W part: C += S_{t-1} @ W^T (A read-only here; one LDS.128 -> two MMAs)
    if (t > 0) {
#pragma unroll
      for (int kt = 0; kt < 8; kt++) {
#pragma unroll
        for (int i = 0; i < 8; i++) {
          uint4 b = Wtab[(kt * 8 + i) * 32];
          mmah(C[2 * i], A[kt], b.x, b.y);
          mmah(C[2 * i + 1], A[kt], b.z, b.w);
        }
      }
    }
    // transform = the move: A（S_t A-fragments) = tanh(C), f16x2 lanes align
    // with the m16n8k16 A layout exactly (C row pairs -> A k-tiles).
#pragma unroll
    for (int kt = 0; kt < 8; kt++) {
      A[kt][0] = th2(C[2 * kt][0]);
      A[kt][1] = th2(C[2 * kt][1]);
      A[kt][2] = th2(C[2 * kt + 1][0]);
      A[kt][3] = th2(C[2 * kt + 1][1]);
    }
  }

  // output: out = S @ V^T + V_b (fp32 accum; N padded to 16, kt stride 32)
  float o0[4], o1[4];
  {
    const uint4* bb = (const uint4*)(sm + OFF_V) + lane;
    uint4 b = bb[0];
    mma16z(o0, A[0], b.x, b.y);
    mma16z(o1, A[0], b.z, b.w);
#pragma unroll
    for (int kt = 1; kt < 8; kt++) {
      b = bb[kt * 32];
      mma16(o0, A[kt], b.x, b.y);
      mma16(o1, A[kt], b.z, b.w);
    }
  }
  const float vb0 = __ldg(Vb + 2 * q), vb1 = __ldg(Vb + 2 * q + 1);
  const int row0 = g * 16 + r;
  *(float2*)(out + row0 * kC + 2 * q) = make_float2(o0[0] + vb0, o0[1] + vb1);
  *(float2*)(out + (row0 + 8) * kC + 2 * q) =
      make_float2(o0[2] + vb0, o0[3] + vb1);
  if (q == 0) {
    const float vb8 = __ldg(Vb + 8), vb9 = __ldg(Vb + 9);
    *(float2*)(out + row0 * kC + 8) = make_float2(o1[0] + vb8, o1[1] + vb9);
    *(float2*)(out + (row0 + 8) * kC + 8) =
        make_float2(o1[2] + vb8, o1[3] + vb9);
  }
}

}  // namespace

extern "C" void kernel_launch(void* const* d_in, const int* in_sizes, int n_in,
                              void* d_out, int out_size) {
  (void)in_sizes; (void)n_in; (void)out_size;
  cudaFuncSetAttribute(rnn_kernel, cudaFuncAttributeMaxDynamicSharedMemorySize,
                       SMEM_TOTAL);
  rnn_kernel<<<GRID, THREADS, SMEM_TOTAL>>>(
      (const float*)d_in[0], (const float*)d_in[1], (const float*)d_in[2],
      (const float*)d_in[3], (const float*)d_in[4], (const float*)d_in[5],
      (const float*)d_in[6], (float*)d_out);
}

// round 13
// speedup vs baseline: 2.3389x; 1.0600x over previous
#include <cuda_runtime.h>
#include <cuda_fp16.h>
#include <cstdint>

#define DI __device__ __forceinline__

namespace {

constexpr int kT = 28;
constexpr int kI = 28;
constexpr int kH = 128;
constexpr int kC = 10;
constexpr int WARPS = 4;
constexpr int THREADS = WARPS * 32;                 // 128
constexpr int TILES = 32768 / 32;                   // 1024 warp-tiles (m32)
constexpr int GRID = TILES / WARPS;                 // 256
constexpr int XROW = kT * kI;                       // 784

// SMEM: paired-B fragment tables. One uint4 per lane per (kt, nt-pair)
// = B fragments for two consecutive n-tiles -> one LDS.128 feeds two MMAs
// (and with m32, each loaded B value feeds FOUR MMAs).
constexpr unsigned OFF_W = 0;                   // [8kt][8ntp][32 lane][16B] = 32768
constexpr unsigned OFF_U = 32768;               // [2kt][8ntp][32][16B]     = 8192
constexpr unsigned OFF_V = 32768 + 8192;        // [8kt][1ntp][32][16B]     = 4096
constexpr unsigned SMEM_TOTAL = OFF_V + 4096;   // 45056 -> 2 CTAs/SM

// pack two fp32 -> fp16x2 (lo = a, hi = b)
DI unsigned packh(float a, float b) {
  unsigned d;
  asm("cvt.rn.f16x2.f32 %0, %1, %2;" : "=r"(d) : "f"(b), "f"(a));
  return d;
}
DI unsigned packh2(float2 v) { return packh(v.x, v.y); }

DI unsigned th2(unsigned h2) {  // tanh on fp16x2, one MUFU per 2 elems
  unsigned r;
  asm("tanh.approx.f16x2 %0, %1;" : "=r"(r) : "r"(h2));
  return r;
}

// f16-accumulator MMA: D(f16x2 x2) += A(m16k16 f16) * B(k16n8 f16)
DI void mmah(unsigned* d, const unsigned* a, unsigned bx, unsigned by) {
  asm("mma.sync.aligned.m16n8k16.row.col.f16.f16.f16.f16 "
      "{%0,%1},{%2,%3,%4,%5},{%6,%7},{%0,%1};"
      : "+r"(d[0]), "+r"(d[1])
      : "r"(a[0]), "r"(a[1]), "r"(a[2]), "r"(a[3]), "r"(bx), "r"(by));
}
DI void mmahz(unsigned* d, const unsigned* a, unsigned bx, unsigned by) {
  asm("mma.sync.aligned.m16n8k16.row.col.f16.f16.f16.f16 "
      "{%0,%1},{%2,%3,%4,%5},{%6,%7},{%8,%8};"
      : "=r"(d[0]), "=r"(d[1])
      : "r"(a[0]), "r"(a[1]), "r"(a[2]), "r"(a[3]), "r"(bx), "r"(by),
        "r"(0u));
}
// f32-accumulator MMA (output projection only, outside the hot loop)
DI void mma16(float* c, const unsigned* a, unsigned bx, unsigned by) {
  asm("mma.sync.aligned.m16n8k16.row.col.f32.f16.f16.f32 "
      "{%0,%1,%2,%3},{%4,%5,%6,%7},{%8,%9},{%0,%1,%2,%3};"
      : "+f"(c[0]), "+f"(c[1]), "+f"(c[2]), "+f"(c[3])
      : "r"(a[0]), "r"(a[1]), "r"(a[2]), "r"(a[3]), "r"(bx), "r"(by));
}
DI void mma16z(float* c, const unsigned* a, unsigned bx, unsigned by) {
  asm("mma.sync.aligned.m16n8k16.row.col.f32.f16.f16.f32 "
      "{%0,%1,%2,%3},{%4,%5,%6,%7},{%8,%9},{%10,%10,%10,%10};"
      : "=f"(c[0]), "=f"(c[1]), "=f"(c[2]), "=f"(c[3])
      : "r"(a[0]), "r"(a[1]), "r"(a[2]), "r"(a[3]), "r"(bx), "r"(by),
        "f"(0.0f));
}

// B element (n,k) -> byte offset inside a paired table with `ntpn` nt-pairs
// (kt stride = ntpn * 32 uint4). W: ntpn=8, U: ntpn=8, V: ntpn=1.
DI unsigned bpos(int n, int k, int ntpn) {
  int kt = k >> 4, kk = k & 15, nt = n >> 3, rr = n & 7;
  int ntp = nt >> 1, sel = nt & 1;
  int ln = rr * 4 + ((kk >> 1) & 3);
  return (unsigned)((((kt * ntpn + ntp) * 32 + ln) << 4) + sel * 8 +
                    ((kk >> 3) & 1) * 4 + (kk & 1) * 2);
}

__global__ void __launch_bounds__(THREADS, 2) rnn_kernel(
    const float* __restrict__ x, const float* __restrict__ Uw,
    const float* __restrict__ Ub, const float* __restrict__ Ww,
    const float* __restrict__ Wb, const float* __restrict__ Vw,
    const float* __restrict__ Vb, float* __restrict__ out) {
  extern __shared__ __align__(16) char sm[];
  const int tid = threadIdx.x;
  const int w = tid >> 5, lane = tid & 31;
  const int r = lane >> 2, q = lane & 3;

  // ---- build fp16 paired-B fragment tables, biases folded into U col 28 ----
  for (int idx = tid; idx < kH * kH; idx += THREADS) {  // W^T[k][n] = Ww[n*128+k]
    int n = idx >> 7, k = idx & 127;
    *(__half*)(sm + OFF_W + bpos(n, k, 8)) = __float2half_rn(Ww[idx]);
  }
  for (int idx = tid; idx < kH * 32; idx += THREADS) {  // U^T padded K=32
    int n = idx >> 5, k = idx & 31;
    float v = (k < kI) ? Uw[n * kI + k] : ((k == kI) ? (Ub[n] + Wb[n]) : 0.0f);
    *(__half*)(sm + OFF_U + bpos(n, k, 8)) = __float2half_rn(v);
  }
  for (int idx = tid; idx < 16 * kH; idx += THREADS) {  // V^T padded N=16
    int n = idx >> 7, k = idx & 127;
    float v = (n < kC) ? Vw[n * kH + k] : 0.0f;
    *(__half*)(sm + OFF_V + bpos(n, k, 1)) = __float2half_rn(v);
  }
  __syncthreads();

  const int g = blockIdx.x * WARPS + w;  // global warp-tile (32 batch rows)

  // lane's A-fragment rows per m-tile: g*32 + m*16 + {r, r+8}
  const float* xbase = x + (long)(g * 32 + r) * XROW;
  const uint4* Utab = (const uint4*)(sm + OFF_U) + lane;
  const uint4* Wtab = (const uint4*)(sm + OFF_W) + lane;

  // A-fragments of [x_t | 1 | 0pad] per m-tile; converted at load
  unsigned xf[2][2][4];
  {
    const unsigned cpad = (q == 2) ? 0x00003C00u : 0u;  // cols 28..31 = 1,0,0,0
    if (q >= 2) {
      xf[0][1][2] = cpad; xf[0][1][3] = cpad;
      xf[1][1][2] = cpad; xf[1][1][3] = cpad;
    }
  }
  auto ldxf = [&](int t) {
#pragma unroll
    for (int m = 0; m < 2; m++) {
      const float* p0 = xbase + (m * 16) * XROW + t * kI + 2 * q;
      const float* p1 = p0 + 8 * XROW;
      xf[m][0][0] = packh2(*(const float2*)(p0));
      xf[m][0][1] = packh2(*(const float2*)(p1));
      xf[m][0][2] = packh2(*(const float2*)(p0 + 8));
      xf[m][0][3] = packh2(*(const float2*)(p1 + 8));
      xf[m][1][0] = packh2(*(const float2*)(p0 + 16));
      xf[m][1][1] = packh2(*(const float2*)(p1 + 16));
      if (q < 2) {  // q>=2 would read past row end on the last row
        xf[m][1][2] = packh2(*(const float2*)(p0 + 24));
        xf[m][1][3] = packh2(*(const float2*)(p1 + 24));
      }
    }
  };
  ldxf(0);

  // Persistent state: S_{t-1} A-fragments (fp16x2), one per m-tile.
  // Single array, no ping-pong (the tanh transform IS the move from C).
  unsigned A[2][8][4];

#pragma unroll 1
  for (int t = 0; t < kT; t++) {
    // Fresh f16x2 accumulators each iteration.
    unsigned C[2][16][2];
    // U part: C = x_t @ U^T (+ biases); kt=0 initializes
#pragma unroll
    for (int i = 0; i < 8; i++) {
      uint4 bb = Utab[i * 32];
#pragma unroll
      for (int m = 0; m < 2; m++) {
        mmahz(C[m][2 * i], xf[m][0], bb.x, bb.y);
        mmahz(C[m][2 * i + 1], xf[m][0], bb.z, bb.w);
      }
    }
#pragma unroll
    for (int i = 0; i < 8; i++) {
      uint4 bb = Utab[256 + i * 32];
#pragma unroll
      for (int m = 0; m < 2; m++) {
        mmah(C[m][2 * i], xf[m][1], bb.x, bb.y);
        mmah(C[m][2 * i + 1], xf[m][1], bb.z, bb.w);
      }
    }
    // prefetch + convert x_{t+1} now (xf dead after U part): the 256 W-MMAs
    // below cover the DRAM latency of these LDGs.
    if (t + 1 < kT) ldxf(t + 1);
    // W part: C += S_{t-1} @ W^T (one LDS.128 feeds FOUR MMAs)
    if (t > 0) {
#pragma unroll
      for (int kt = 0; kt < 8; kt++) {
#pragma unroll
        for (int i = 0; i < 8; i++) {
          uint4 b = Wtab[(kt * 8 + i) * 32];
#pragma unroll
          for (int m = 0; m < 2; m++) {
            mmah(C[m][2 * i], A[m][kt], b.x, b.y);
            mmah(C[m][2 * i + 1], A[m][kt], b.z, b.w);
          }
        }
      }
    }
    // transform = the move: A = tanh(C); f16x2 C rows align with A k-tiles.
#pragma unroll
    for (int m = 0; m < 2; m++)
#pragma unroll
      for (int kt = 0; kt < 8; kt++) {
        A[m][kt][0] = th2(C[m][2 * kt][0]);
        A[m][kt][1] = th2(C[m][2 * kt][1]);
        A[m][kt][2] = th2(C[m][2 * kt + 1][0]);
        A[m][kt][3] = th2(C[m][2 * kt + 1][1]);
      }
  }

  // output: out = S @ V^T + V_b (fp32 accum; N padded to 16, kt stride 32)
  const float vb0 = __ldg(Vb + 2 * q), vb1 = __ldg(Vb + 2 * q + 1);
  const float vb8 = __ldg(Vb + 8), vb9 = __ldg(Vb + 9);
#pragma unroll
  for (int m = 0; m < 2; m++) {
    float o0[4], o1[4];
    const uint4* bb = (const uint4*)(sm + OFF_V) + lane;
    uint4 b = bb[0];
    mma16z(o0, A[m][0], b.x, b.y);
    mma16z(o1, A[m][0], b.z, b.w);
#pragma unroll
    for (int kt = 1; kt < 8; kt++) {
      b = bb[kt * 32];
      mma16(o0, A[m][kt], b.x, b.y);
      mma16(o1, A[m][kt], b.z, b.w);
    }
    const int row0 = g * 32 + m * 16 + r;
    *(float2*)(out + row0 * kC + 2 * q) = make_float2(o0[0] + vb0, o0[1] + vb1);
    *(float2*)(out + (row0 + 8) * kC + 2 * q) =
        make_float2(o0[2] + vb0, o0[3] + vb1);
    if (q == 0) {
      *(float2*)(out + row0 * kC + 8) = make_float2(o1[0] + vb8, o1[1] + vb9);
      *(float2*)(out + (row0 + 8) * kC + 8) =
          make_float2(o1[2] + vb8, o1[3] + vb9);
    }
  }
}

}  // namespace

extern "C" void kernel_launch(void* const* d_in, const int* in_sizes, int n_in,
                              void* d_out, int out_size) {
  (void)in_sizes; (void)n_in; (void)out_size;
  cudaFuncSetAttribute(rnn_kernel, cudaFuncAttributeMaxDynamicSharedMemorySize,
                       SMEM_TOTAL);
  rnn_kernel<<<GRID, THREADS, SMEM_TOTAL>>>(
      (const float*)d_in[0], (const float*)d_in[1], (const float*)d_in[2],
      (const float*)d_in[3], (const float*)d_in[4], (const float*)d_in[5],
      (const float*)d_in[6], (float*)d_out);
}